// round 13
// baseline (speedup 1.0000x reference)
#include <cuda_runtime.h>
#include <cuda.h>
#include <cstdint>

// ============================================================================
// MultiLoraLinear on GB300 (ptxas target = plain sm_103, so NO tcgen05).
// Prologue kernel converts W fp32 -> f16 scratch (8MB __device__ array).
// Main: TMA + mbarrier pipeline -> SMEM -> mma.sync m16n8k16 f16.
//   out[b, s, o] = sum_i x[b, s, i] * weight[adapter_ids[b], o, i]
// B=8, S=2048, IN=4096, OUT=64, L=16, fp32 in/out.
//
// R13 = R12 with the compile fix (scratch declared as uint16_t; no
// cuda_fp16.h dependence -- all f16 values handled as raw bits).
// R12 theory vs R11 (54.0us; stage time == per-SM LTS delivery floor):
//   Cut LTS bytes: pre-convert W to f16 ONCE (prologue ~3-4us), TMA f16.
//   - stage 49152 -> 40960 B => LTS floor 1154 -> 962 cyc
//   - B frags native f16, natural k-order: 2x LDS.32 per nt, NO cvt
//   - A frags via ld.shared.v2.f32 + 1 cvt each, same natural k-order
//   - consumer ~55 instr/warp/stage (was ~90); NSTAGE 4 -> 5 (206KB)
//   Numerics unchanged (same rne f16 conversion of W, done once).
// ============================================================================

#define DEVINL __device__ __forceinline__

namespace mlora {

constexpr int kB = 8, kS = 2048, kIN = 4096, kOUT = 64, kL = 16;
constexpr int TILE_M = 128;           // x rows per CTA
constexpr int TILE_K = 64;            // K elems per pipeline stage
constexpr int NITER  = kIN / TILE_K;  // 64
constexpr int NSTAGE = 5;

// Each stage: A = [128 rows x 64 k] fp32 as two [128 x 32] sub-tiles
// (128B rows, TMA SW128); B(W) = [64 rows x 64 k] f16, ONE tile, 128B rows.
constexpr int A_SUB   = TILE_M * 32 * 4;        // 16384
constexpr int A_BYTES = 2 * A_SUB;              // 32768
constexpr int B_BYTES = kOUT * TILE_K * 2;      //  8192 (f16)
constexpr int STAGE_BYTES = A_BYTES + B_BYTES;  // 40960

constexpr int OFF_FULL  = 0;
constexpr int OFF_EMPTY = OFF_FULL + NSTAGE * 8;
constexpr int OFF_DATA  = 1024;                              // SW128 alignment
constexpr int SMEM_TOTAL = OFF_DATA + NSTAGE * STAGE_BYTES;  // 205824

constexpr int NTHREADS = 544;          // 16 compute warps + 1 TMA warp
constexpr int W_ELEMS  = kL * kOUT * kIN;   // 4,194,304

}  // namespace mlora

// 8MB f16 scratch for converted weights ([L][OUT][IN], IN contiguous).
// Stored as raw 16-bit payloads; no fp16 header types needed.
__device__ __align__(16) uint16_t g_wf16[mlora::W_ELEMS];

namespace mlora {

DEVINL uint32_t smem_u32(const void* p) {
    uint32_t a;
    asm("{ .reg .u64 t; cvta.to.shared.u64 t, %1; cvt.u32.u64 %0, t; }"
        : "=r"(a) : "l"(p));
    return a;
}

DEVINL uint32_t elect_one() {
    uint32_t pred;
    asm volatile(
        "{\n\t.reg .pred p;\n\telect.sync _|p, 0xFFFFFFFF;\n\t"
        "selp.b32 %0, 1, 0, p;\n\t}"
        : "=r"(pred));
    return pred;
}

#define MBARRIER_INIT(mbar, count) \
    asm volatile("mbarrier.init.shared.b64 [%0], %1;" \
        :: "r"((uint32_t)(mbar)), "r"((uint32_t)(count)) : "memory")

#define MBARRIER_ARRIVE(mbar) \
    asm volatile("mbarrier.arrive.shared.b64 _, [%0];" \
        :: "r"((uint32_t)(mbar)) : "memory")

#define MBARRIER_EXPECT_TX(mbar, bytes) \
    asm volatile("mbarrier.arrive.expect_tx.shared.b64 _, [%0], %1;" \
        :: "r"((uint32_t)(mbar)), "r"((uint32_t)(bytes)) : "memory")

#define MBARRIER_WAIT_PARITY(mbar, parity) do {                                   \
    uint32_t _m = (uint32_t)(mbar);                                               \
    uint32_t _p = (uint32_t)(parity);                                             \
    uint32_t _done;                                                               \
    asm volatile(                                                                 \
        "{\n\t.reg .pred p;\n\t"                                                  \
        "mbarrier.try_wait.parity.acquire.cta.shared::cta.b64 p, [%1], %2;\n\t"   \
        "selp.b32 %0, 1, 0, p;\n\t}"                                              \
        : "=r"(_done) : "r"(_m), "r"(_p) : "memory");                             \
    if (!_done) {                                                                 \
        asm volatile(                                                             \
            "{\n\t.reg .pred P1;\n\t"                                             \
            "WAIT_LOOP_%=:\n\t"                                                   \
            "mbarrier.try_wait.parity.acquire.cta.shared::cta.b64 P1, [%0], %1, 0x989680;\n\t" \
            "@P1 bra.uni WAIT_DONE_%=;\n\t"                                       \
            "bra.uni WAIT_LOOP_%=;\n\t"                                           \
            "WAIT_DONE_%=:\n\t}"                                                  \
            :: "r"(_m), "r"(_p) : "memory");                                      \
    }                                                                             \
} while (0)

// Producer-side wait: post-wait SMEM writes are async-proxy (TMA) only.
#define MBARRIER_WAIT_PARITY_RELAXED(mbar, parity) do {                           \
    uint32_t _m = (uint32_t)(mbar);                                               \
    uint32_t _p = (uint32_t)(parity);                                             \
    uint32_t _done;                                                               \
    asm volatile(                                                                 \
        "{\n\t.reg .pred p;\n\t"                                                  \
        "mbarrier.try_wait.parity.relaxed.cta.shared::cta.b64 p, [%1], %2, 0x989680;\n\t" \
        "selp.b32 %0, 1, 0, p;\n\t}"                                              \
        : "=r"(_done) : "r"(_m), "r"(_p) : "memory");                             \
    if (!_done) {                                                                 \
        asm volatile(                                                             \
            "{\n\t.reg .pred P1;\n\t"                                             \
            "WAIT_LOOP_%=:\n\t"                                                   \
            "mbarrier.try_wait.parity.relaxed.cta.shared::cta.b64 P1, [%0], %1, 0x989680;\n\t" \
            "@P1 bra.uni WAIT_DONE_%=;\n\t"                                       \
            "bra.uni WAIT_LOOP_%=;\n\t"                                           \
            "WAIT_DONE_%=:\n\t}"                                                  \
            :: "r"(_m), "r"(_p) : "memory");                                      \
    }                                                                             \
} while (0)

#define TMA_LOAD_3D(smem_addr, tensor_map, cx, cy, cz, mbar) \
    asm volatile( \
        "cp.async.bulk.tensor.3d.shared::cta.global.tile.mbarrier::complete_tx::bytes " \
        "[%0], [%1, {%2, %3, %4}], [%5];" \
        :: "r"((uint32_t)(smem_addr)), "l"(tensor_map), \
           "r"((int32_t)(cx)), "r"((int32_t)(cy)), "r"((int32_t)(cz)), \
           "r"((uint32_t)(mbar)) \
        : "memory")

// Pack two f32 into one f16x2 register (rne): low half = vlo, high = vhi.
#define CVT_F16X2(dst, vlo, vhi) \
    asm("cvt.rn.f16x2.f32 %0, %1, %2;" : "=r"(dst) : "f"(vhi), "f"(vlo))

// m16n8k16 f16 MMA, fp32 accumulate (baseline PTX; fallback HMMA on sm_103).
#define MMA_F16(d, a, b) \
    asm volatile( \
        "mma.sync.aligned.m16n8k16.row.col.f32.f16.f16.f32 " \
        "{%0,%1,%2,%3}, {%4,%5,%6,%7}, {%8,%9}, {%0,%1,%2,%3};" \
        : "+f"((d)[0]), "+f"((d)[1]), "+f"((d)[2]), "+f"((d)[3]) \
        : "r"((a)[0]), "r"((a)[1]), "r"((a)[2]), "r"((a)[3]), \
          "r"((b)[0]), "r"((b)[1]))

// ============================================================================
// Prologue: convert weight fp32 -> f16 scratch (rne, same as the old per-use
// conversion, so numerics are unchanged). 1M threads x float4.
// ============================================================================
__global__ void convert_w_kernel(const float4* __restrict__ w,
                                 uint2* __restrict__ dst) {
    const int i = blockIdx.x * blockDim.x + threadIdx.x;   // < W_ELEMS/4
    const float4 v = w[i];
    uint32_t lo, hi;
    CVT_F16X2(lo, v.x, v.y);
    CVT_F16X2(hi, v.z, v.w);
    dst[i] = make_uint2(lo, hi);
}

// ============================================================================
// Main kernel: 544 threads. Warps 0-15 compute: warp w = (mh=w&3, kq=w>>2)
// owns rows [mh*32,+32) x all 64 cols over k16 slice kq of each stage.
// Natural k-order in both fragments (B is raw f16). Warp 16 = TMA producer.
// grid = B * (S/128) = 128. blockIdx.x = b*16 + tile. 1 CTA per SM.
// ============================================================================
__global__ void __launch_bounds__(NTHREADS, 1) mlora_kernel(
    const __grid_constant__ CUtensorMap mapX,
    const __grid_constant__ CUtensorMap mapW,
    const int* __restrict__ adapter_ids,
    float* __restrict__ out)
{
    extern __shared__ char smem[];
    const uint32_t sb = smem_u32(smem);
    const int tid  = threadIdx.x;
    const int wid  = tid >> 5;
    const int lid  = tid & 31;
    const int b    = blockIdx.x >> 4;
    const int tile = blockIdx.x & 15;

    if (tid == 0) {
        #pragma unroll
        for (int s = 0; s < NSTAGE; s++) {
            MBARRIER_INIT(sb + OFF_FULL  + s * 8, 1);   // completed by TMA tx bytes
            MBARRIER_INIT(sb + OFF_EMPTY + s * 8, 16);  // 16 consumer warps arrive
        }
    }
    __syncthreads();

    if (wid == 16) {
        // ---------------- TMA producer ----------------
        if (elect_one()) {
            const int aid = adapter_ids[b];
            int st = 0, ph = 1;  // parity 1: fresh empty barriers pass immediately
            for (int it = 0; it < NITER; it++) {
                MBARRIER_WAIT_PARITY_RELAXED(sb + OFF_EMPTY + st * 8, ph);
                const uint32_t full = sb + OFF_FULL + st * 8;
                MBARRIER_EXPECT_TX(full, STAGE_BYTES);
                const uint32_t base = sb + OFF_DATA + st * STAGE_BYTES;
                #pragma unroll
                for (int t = 0; t < 2; t++) {
                    TMA_LOAD_3D(base + t * A_SUB, &mapX,
                                it * TILE_K + t * 32, tile * TILE_M, b, full);
                }
                TMA_LOAD_3D(base + A_BYTES, &mapW, it * TILE_K, 0, aid, full);
                if (++st == NSTAGE) { st = 0; ph ^= 1; }
            }
        }
        return;
    }

    // ---------------- compute warps (wid 0..15) ----------------
    // Warp (mh, kq): rows [mh*32,+32) x cols [0,64), k16 slice kq.
    // A: fp32, two [128x32] sub-tiles, 128B rows, SW128 (granule g of row r
    //    lands at g ^ (r&7)). Natural k-order fragments via ld.shared.v2.f32:
    //    a0 = k(2c,2c+1) at bytes grp*64+8c; a2 = +32; a1/a3 = row+8 (+1024B).
    // B: f16, one [64 rows x 64 k] tile, 128B rows, SW128. b0 = k(2c,2c+1) at
    //    bytes kq*32+4c (one LDS.32, already f16x2!); b1 = +16 bytes.
    const int mh   = wid & 3;         // 0..3: 32-row band
    const int kq   = wid >> 2;        // 0..3: k16 slice
    const int ksub = kq >> 1;         // which 32-k A sub-tile
    const int grp  = kq & 1;          // which k16 group within the A sub-tile
    const int c    = lid & 3;
    const uint32_t sw   = (uint32_t)(lid >> 2) << 4;    // swizzle XOR (row&7)*16
    const uint32_t aRow = (uint32_t)(mh * 32 + (lid >> 2));
    const uint32_t bRow = (uint32_t)(lid >> 2);

    // Constant per-warp byte offsets (within a 128B row, pre-XORed with sw).
    // No low-bit carries interact with the XORs (verified: 8c<=24, 4c<=12).
    const uint32_t aOff0 = ((uint32_t)(grp * 64 + 8 * c)) ^ sw;   // a0: k 2c,2c+1
    const uint32_t aOff2 = aOff0 ^ 32u;                            // a2: k +8
    const uint32_t bOff0 = ((uint32_t)(kq * 32 + 4 * c)) ^ sw;    // b0: k 2c,2c+1
    const uint32_t bOff1 = bOff0 ^ 16u;                            // b1: k +8

    float acc[2][8][4];   // [mt 16-row tiles][nt 8-col tiles][frag] = 64 regs
    #pragma unroll
    for (int mt = 0; mt < 2; mt++)
        #pragma unroll
        for (int nt = 0; nt < 8; nt++)
            #pragma unroll
            for (int i = 0; i < 4; i++) acc[mt][nt][i] = 0.0f;

    int st = 0, ph = 0;
    for (int it = 0; it < NITER; it++) {
        MBARRIER_WAIT_PARITY(sb + OFF_FULL + st * 8, ph);
        const char* base  = smem + OFF_DATA + st * STAGE_BYTES;
        const char* aBase = base + ksub * A_SUB;
        const char* bBase = base + A_BYTES;

        // B fragments: 8 n-tiles x 2 LDS.32, raw f16x2, no conversion.
        uint32_t bf[8][2];
        #pragma unroll
        for (int nt = 0; nt < 8; nt++) {
            const char* rp = bBase + (bRow + nt * 8) * 128;
            bf[nt][0] = *reinterpret_cast<const uint32_t*>(rp + bOff0);
            bf[nt][1] = *reinterpret_cast<const uint32_t*>(rp + bOff1);
        }

        #pragma unroll
        for (int mt = 0; mt < 2; mt++) {
            const char* ap = aBase + (aRow + mt * 16) * 128;
            const float2 f0 = *reinterpret_cast<const float2*>(ap + aOff0);
            const float2 f1 = *reinterpret_cast<const float2*>(ap + 1024 + aOff0);
            const float2 f2 = *reinterpret_cast<const float2*>(ap + aOff2);
            const float2 f3 = *reinterpret_cast<const float2*>(ap + 1024 + aOff2);
            uint32_t af[4];
            CVT_F16X2(af[0], f0.x, f0.y);
            CVT_F16X2(af[1], f1.x, f1.y);
            CVT_F16X2(af[2], f2.x, f2.y);
            CVT_F16X2(af[3], f3.x, f3.y);
            #pragma unroll
            for (int nt = 0; nt < 8; nt++)
                MMA_F16(acc[mt][nt], af, bf[nt]);
        }

        // HMMA issue implies all this stage's LDS completed -> safe to recycle.
        __syncwarp();
        if (lid == 0) MBARRIER_ARRIVE(sb + OFF_EMPTY + st * 8);
        if (++st == NSTAGE) { st = 0; ph ^= 1; }
    }

    // ---------------- 4-way cross-k reduction + epilogue ----------------
    // The 4 warps sharing mh reduce. kq=1..3 dump acc to SMEM ([j][lane],
    // conflict-free); after bar.sync, kq=0 sums 3 buffers + own acc, writes
    // GMEM. Stage data area is dead by now (12 x 8KB = 96KB < 200KB).
    {
        asm volatile("bar.sync 1, 512;" ::: "memory");   // all loop reads done
        float* redBase = reinterpret_cast<float*>(smem + OFF_DATA);
        if (kq != 0) {
            float* myBuf = redBase + (mh * 3 + (kq - 1)) * 2048;
            #pragma unroll
            for (int mt = 0; mt < 2; mt++)
                #pragma unroll
                for (int nt = 0; nt < 8; nt++)
                    #pragma unroll
                    for (int i = 0; i < 4; i++)
                        myBuf[((mt * 8 + nt) * 4 + i) * 32 + lid] = acc[mt][nt][i];
        }
        asm volatile("bar.sync 1, 512;" ::: "memory");
        if (kq == 0) {
            const float* r0 = redBase + (mh * 3 + 0) * 2048;
            const float* r1 = redBase + (mh * 3 + 1) * 2048;
            const float* r2 = redBase + (mh * 3 + 2) * 2048;
            #pragma unroll
            for (int mt = 0; mt < 2; mt++)
                #pragma unroll
                for (int nt = 0; nt < 8; nt++)
                    #pragma unroll
                    for (int i = 0; i < 4; i++) {
                        const int j = ((mt * 8 + nt) * 4 + i) * 32 + lid;
                        acc[mt][nt][i] += r0[j] + r1[j] + r2[j];
                    }

            // c0,c1 -> (row = lane/4, cols 2*(lane%4)+{0,1}); c2,c3 -> row+8.
            const size_t rowBase = (size_t)b * kS + (size_t)tile * TILE_M
                                 + (size_t)(mh * 32) + (size_t)(lid >> 2);
            const int colBase = (lid & 3) * 2;
            #pragma unroll
            for (int mt = 0; mt < 2; mt++) {
                #pragma unroll
                for (int nt = 0; nt < 8; nt++) {
                    const size_t r0w = rowBase + mt * 16;
                    float* p0 = out + r0w * kOUT + nt * 8 + colBase;
                    float* p1 = out + (r0w + 8) * kOUT + nt * 8 + colBase;
                    *reinterpret_cast<float2*>(p0) =
                        make_float2(acc[mt][nt][0], acc[mt][nt][1]);
                    *reinterpret_cast<float2*>(p1) =
                        make_float2(acc[mt][nt][2], acc[mt][nt][3]);
                }
            }
        }
    }
}

}  // namespace mlora

// ============================================================================
// Host side
// ============================================================================

typedef CUresult (*PFN_encodeTiled)(
    CUtensorMap*, CUtensorMapDataType, cuuint32_t, void*,
    const cuuint64_t*, const cuuint64_t*, const cuuint32_t*, const cuuint32_t*,
    CUtensorMapInterleave, CUtensorMapSwizzle, CUtensorMapL2promotion,
    CUtensorMapFloatOOBfill);

extern "C" void kernel_launch(void* const* d_in, const int* in_sizes, int n_in,
                              void* d_out, int out_size) {
    (void)in_sizes; (void)n_in; (void)out_size;
    const float* x   = (const float*)d_in[0];
    const int*   ids = (const int*)  d_in[1];
    const float* w   = (const float*)d_in[2];
    float*       out = (float*)d_out;

    PFN_encodeTiled enc = nullptr;
    {
        void* p = nullptr;
        cudaDriverEntryPointQueryResult qr;
#if CUDART_VERSION >= 12050
        cudaGetDriverEntryPointByVersion("cuTensorMapEncodeTiled", &p, 12000,
                                         cudaEnableDefault, &qr);
#else
        cudaGetDriverEntryPoint("cuTensorMapEncodeTiled", &p, cudaEnableDefault, &qr);
#endif
        enc = (PFN_encodeTiled)p;
    }

    void* wf16 = nullptr;
    cudaGetSymbolAddress(&wf16, g_wf16);

    CUtensorMap mapX, mapW;
    {
        // x: [B, S, IN] fp32 contiguous; dim0 = IN. Box = 32 x 128 (128B rows, SW128).
        cuuint64_t dims[3]    = {(cuuint64_t)mlora::kIN, (cuuint64_t)mlora::kS,
                                 (cuuint64_t)mlora::kB};
        cuuint64_t strides[2] = {(cuuint64_t)mlora::kIN * 4,
                                 (cuuint64_t)mlora::kS * mlora::kIN * 4};
        cuuint32_t box[3]     = {32, (cuuint32_t)mlora::TILE_M, 1};
        cuuint32_t es[3]      = {1, 1, 1};
        enc(&mapX, CU_TENSOR_MAP_DATA_TYPE_FLOAT32, 3, (void*)x,
            dims, strides, box, es,
            CU_TENSOR_MAP_INTERLEAVE_NONE, CU_TENSOR_MAP_SWIZZLE_128B,
            CU_TENSOR_MAP_L2_PROMOTION_L2_128B, CU_TENSOR_MAP_FLOAT_OOB_FILL_NONE);
    }
    {
        // wf16: [L, OUT, IN] f16 contiguous; dim0 = IN. Box = 64 x 64 (128B rows, SW128).
        cuuint64_t dims[3]    = {(cuuint64_t)mlora::kIN, (cuuint64_t)mlora::kOUT,
                                 (cuuint64_t)mlora::kL};
        cuuint64_t strides[2] = {(cuuint64_t)mlora::kIN * 2,
                                 (cuuint64_t)mlora::kOUT * mlora::kIN * 2};
        cuuint32_t box[3]     = {(cuuint32_t)mlora::TILE_K, (cuuint32_t)mlora::kOUT, 1};
        cuuint32_t es[3]      = {1, 1, 1};
        enc(&mapW, CU_TENSOR_MAP_DATA_TYPE_FLOAT16, 3, wf16,
            dims, strides, box, es,
            CU_TENSOR_MAP_INTERLEAVE_NONE, CU_TENSOR_MAP_SWIZZLE_128B,
            CU_TENSOR_MAP_L2_PROMOTION_L2_128B, CU_TENSOR_MAP_FLOAT_OOB_FILL_NONE);
    }

    // Prologue: convert W fp32 -> f16 scratch (stream-ordered before main).
    {
        const int n4 = mlora::W_ELEMS / 4;            // 1,048,576 float4s
        mlora::convert_w_kernel<<<n4 / 256, 256>>>(
            (const float4*)w, (uint2*)wf16);
    }

    cudaFuncSetAttribute(mlora::mlora_kernel,
                         cudaFuncAttributeMaxDynamicSharedMemorySize,
                         mlora::SMEM_TOTAL);

    const int grid = mlora::kB * (mlora::kS / mlora::TILE_M);  // 128
    mlora::mlora_kernel<<<grid, mlora::NTHREADS, mlora::SMEM_TOTAL>>>(
        mapX, mapW, ids, out);
}

// round 14
// speedup vs baseline: 1.0316x; 1.0316x over previous
#include <cuda_runtime.h>
#include <cuda.h>
#include <cstdint>

// ============================================================================
// MultiLoraLinear on GB300 (ptxas target = plain sm_103, so NO tcgen05).
// Prologue kernel converts ONLY the referenced adapters' W fp32 -> f16
// scratch (deduped, 128 blocks, ~1.7us). Main: TMA + mbarrier pipeline ->
// SMEM -> mma.sync m16n8k16 f16.
//   out[b, s, o] = sum_i x[b, s, i] * weight[adapter_ids[b], o, i]
// B=8, S=2048, IN=4096, OUT=64, L=16, fp32 in/out.
//
// R14 vs R13 (bench 57.5us = main 49.2us + prologue 8.3us tax per replay):
//   Main kernel unchanged (best engine: 40KB stages, f16 W, ~55 instr/warp).
//   Prologue: convert only adapters in adapter_ids (<=8 of 16), deduped,
//   grid 128 (8 b x 16 slices) -> <=12MB at full-chip BW ~= 1.7us.
// ============================================================================

#define DEVINL __device__ __forceinline__

namespace mlora {

constexpr int kB = 8, kS = 2048, kIN = 4096, kOUT = 64, kL = 16;
constexpr int TILE_M = 128;           // x rows per CTA
constexpr int TILE_K = 64;            // K elems per pipeline stage
constexpr int NITER  = kIN / TILE_K;  // 64
constexpr int NSTAGE = 5;

// Each stage: A = [128 rows x 64 k] fp32 as two [128 x 32] sub-tiles
// (128B rows, TMA SW128); B(W) = [64 rows x 64 k] f16, ONE tile, 128B rows.
constexpr int A_SUB   = TILE_M * 32 * 4;        // 16384
constexpr int A_BYTES = 2 * A_SUB;              // 32768
constexpr int B_BYTES = kOUT * TILE_K * 2;      //  8192 (f16)
constexpr int STAGE_BYTES = A_BYTES + B_BYTES;  // 40960

constexpr int OFF_FULL  = 0;
constexpr int OFF_EMPTY = OFF_FULL + NSTAGE * 8;
constexpr int OFF_DATA  = 1024;                              // SW128 alignment
constexpr int SMEM_TOTAL = OFF_DATA + NSTAGE * STAGE_BYTES;  // 205824

constexpr int NTHREADS = 544;          // 16 compute warps + 1 TMA warp
constexpr int W_ELEMS  = kL * kOUT * kIN;   // 4,194,304
constexpr int W_PER_AD = kOUT * kIN;        // 262,144 floats per adapter

}  // namespace mlora

// 8MB f16 scratch for converted weights ([L][OUT][IN], IN contiguous).
// Stored as raw 16-bit payloads; no fp16 header types needed.
__device__ __align__(16) uint16_t g_wf16[mlora::W_ELEMS];

namespace mlora {

DEVINL uint32_t smem_u32(const void* p) {
    uint32_t a;
    asm("{ .reg .u64 t; cvta.to.shared.u64 t, %1; cvt.u32.u64 %0, t; }"
        : "=r"(a) : "l"(p));
    return a;
}

DEVINL uint32_t elect_one() {
    uint32_t pred;
    asm volatile(
        "{\n\t.reg .pred p;\n\telect.sync _|p, 0xFFFFFFFF;\n\t"
        "selp.b32 %0, 1, 0, p;\n\t}"
        : "=r"(pred));
    return pred;
}

#define MBARRIER_INIT(mbar, count) \
    asm volatile("mbarrier.init.shared.b64 [%0], %1;" \
        :: "r"((uint32_t)(mbar)), "r"((uint32_t)(count)) : "memory")

#define MBARRIER_ARRIVE(mbar) \
    asm volatile("mbarrier.arrive.shared.b64 _, [%0];" \
        :: "r"((uint32_t)(mbar)) : "memory")

#define MBARRIER_EXPECT_TX(mbar, bytes) \
    asm volatile("mbarrier.arrive.expect_tx.shared.b64 _, [%0], %1;" \
        :: "r"((uint32_t)(mbar)), "r"((uint32_t)(bytes)) : "memory")

#define MBARRIER_WAIT_PARITY(mbar, parity) do {                                   \
    uint32_t _m = (uint32_t)(mbar);                                               \
    uint32_t _p = (uint32_t)(parity);                                             \
    uint32_t _done;                                                               \
    asm volatile(                                                                 \
        "{\n\t.reg .pred p;\n\t"                                                  \
        "mbarrier.try_wait.parity.acquire.cta.shared::cta.b64 p, [%1], %2;\n\t"   \
        "selp.b32 %0, 1, 0, p;\n\t}"                                              \
        : "=r"(_done) : "r"(_m), "r"(_p) : "memory");                             \
    if (!_done) {                                                                 \
        asm volatile(                                                             \
            "{\n\t.reg .pred P1;\n\t"                                             \
            "WAIT_LOOP_%=:\n\t"                                                   \
            "mbarrier.try_wait.parity.acquire.cta.shared::cta.b64 P1, [%0], %1, 0x989680;\n\t" \
            "@P1 bra.uni WAIT_DONE_%=;\n\t"                                       \
            "bra.uni WAIT_LOOP_%=;\n\t"                                           \
            "WAIT_DONE_%=:\n\t}"                                                  \
            :: "r"(_m), "r"(_p) : "memory");                                      \
    }                                                                             \
} while (0)

// Producer-side wait: post-wait SMEM writes are async-proxy (TMA) only.
#define MBARRIER_WAIT_PARITY_RELAXED(mbar, parity) do {                           \
    uint32_t _m = (uint32_t)(mbar);                                               \
    uint32_t _p = (uint32_t)(parity);                                             \
    uint32_t _done;                                                               \
    asm volatile(                                                                 \
        "{\n\t.reg .pred p;\n\t"                                                  \
        "mbarrier.try_wait.parity.relaxed.cta.shared::cta.b64 p, [%1], %2, 0x989680;\n\t" \
        "selp.b32 %0, 1, 0, p;\n\t}"                                              \
        : "=r"(_done) : "r"(_m), "r"(_p) : "memory");                             \
    if (!_done) {                                                                 \
        asm volatile(                                                             \
            "{\n\t.reg .pred P1;\n\t"                                             \
            "WAIT_LOOP_%=:\n\t"                                                   \
            "mbarrier.try_wait.parity.relaxed.cta.shared::cta.b64 P1, [%0], %1, 0x989680;\n\t" \
            "@P1 bra.uni WAIT_DONE_%=;\n\t"                                       \
            "bra.uni WAIT_LOOP_%=;\n\t"                                           \
            "WAIT_DONE_%=:\n\t}"                                                  \
            :: "r"(_m), "r"(_p) : "memory");                                      \
    }                                                                             \
} while (0)

#define TMA_LOAD_3D(smem_addr, tensor_map, cx, cy, cz, mbar) \
    asm volatile( \
        "cp.async.bulk.tensor.3d.shared::cta.global.tile.mbarrier::complete_tx::bytes " \
        "[%0], [%1, {%2, %3, %4}], [%5];" \
        :: "r"((uint32_t)(smem_addr)), "l"(tensor_map), \
           "r"((int32_t)(cx)), "r"((int32_t)(cy)), "r"((int32_t)(cz)), \
           "r"((uint32_t)(mbar)) \
        : "memory")

// Pack two f32 into one f16x2 register (rne): low half = vlo, high = vhi.
#define CVT_F16X2(dst, vlo, vhi) \
    asm("cvt.rn.f16x2.f32 %0, %1, %2;" : "=r"(dst) : "f"(vhi), "f"(vlo))

// m16n8k16 f16 MMA, fp32 accumulate (baseline PTX; fallback HMMA on sm_103).
#define MMA_F16(d, a, b) \
    asm volatile( \
        "mma.sync.aligned.m16n8k16.row.col.f32.f16.f16.f32 " \
        "{%0,%1,%2,%3}, {%4,%5,%6,%7}, {%8,%9}, {%0,%1,%2,%3};" \
        : "+f"((d)[0]), "+f"((d)[1]), "+f"((d)[2]), "+f"((d)[3]) \
        : "r"((a)[0]), "r"((a)[1]), "r"((a)[2]), "r"((a)[3]), \
          "r"((b)[0]), "r"((b)[1]))

// ============================================================================
// Prologue: convert ONLY referenced adapters' W fp32 -> f16 (rne; numerics
// identical to converting at use). Grid = 8 batches x 16 slices = 128 blocks.
// Dedupe: the lowest batch index holding an adapter converts it.
// ============================================================================
__global__ void convert_w_kernel(const float4* __restrict__ w,
                                 uint2* __restrict__ dst,
                                 const int* __restrict__ ids) {
    const int b     = blockIdx.x >> 4;    // 0..7
    const int slice = blockIdx.x & 15;    // 0..15
    const int aid   = ids[b];
    for (int bb = 0; bb < b; bb++)
        if (ids[bb] == aid) return;        // another batch owns this adapter

    constexpr int PER = (kOUT * kIN / 4) / 16;   // 4096 float4 per slice
    const float4* src = w   + (size_t)aid * (kOUT * kIN / 4) + (size_t)slice * PER;
    uint2*        d   = dst + (size_t)aid * (kOUT * kIN / 4) + (size_t)slice * PER;
    #pragma unroll 4
    for (int i = threadIdx.x; i < PER; i += blockDim.x) {
        const float4 v = src[i];
        uint32_t lo, hi;
        CVT_F16X2(lo, v.x, v.y);
        CVT_F16X2(hi, v.z, v.w);
        d[i] = make_uint2(lo, hi);
    }
}

// ============================================================================
// Main kernel: 544 threads. Warps 0-15 compute: warp w = (mh=w&3, kq=w>>2)
// owns rows [mh*32,+32) x all 64 cols over k16 slice kq of each stage.
// Natural k-order in both fragments (B is raw f16). Warp 16 = TMA producer.
// grid = B * (S/128) = 128. blockIdx.x = b*16 + tile. 1 CTA per SM.
// ============================================================================
__global__ void __launch_bounds__(NTHREADS, 1) mlora_kernel(
    const __grid_constant__ CUtensorMap mapX,
    const __grid_constant__ CUtensorMap mapW,
    const int* __restrict__ adapter_ids,
    float* __restrict__ out)
{
    extern __shared__ char smem[];
    const uint32_t sb = smem_u32(smem);
    const int tid  = threadIdx.x;
    const int wid  = tid >> 5;
    const int lid  = tid & 31;
    const int b    = blockIdx.x >> 4;
    const int tile = blockIdx.x & 15;

    if (tid == 0) {
        #pragma unroll
        for (int s = 0; s < NSTAGE; s++) {
            MBARRIER_INIT(sb + OFF_FULL  + s * 8, 1);   // completed by TMA tx bytes
            MBARRIER_INIT(sb + OFF_EMPTY + s * 8, 16);  // 16 consumer warps arrive
        }
    }
    __syncthreads();

    if (wid == 16) {
        // ---------------- TMA producer ----------------
        if (elect_one()) {
            const int aid = adapter_ids[b];
            int st = 0, ph = 1;  // parity 1: fresh empty barriers pass immediately
            for (int it = 0; it < NITER; it++) {
                MBARRIER_WAIT_PARITY_RELAXED(sb + OFF_EMPTY + st * 8, ph);
                const uint32_t full = sb + OFF_FULL + st * 8;
                MBARRIER_EXPECT_TX(full, STAGE_BYTES);
                const uint32_t base = sb + OFF_DATA + st * STAGE_BYTES;
                #pragma unroll
                for (int t = 0; t < 2; t++) {
                    TMA_LOAD_3D(base + t * A_SUB, &mapX,
                                it * TILE_K + t * 32, tile * TILE_M, b, full);
                }
                TMA_LOAD_3D(base + A_BYTES, &mapW, it * TILE_K, 0, aid, full);
                if (++st == NSTAGE) { st = 0; ph ^= 1; }
            }
        }
        return;
    }

    // ---------------- compute warps (wid 0..15) ----------------
    // Warp (mh, kq): rows [mh*32,+32) x cols [0,64), k16 slice kq.
    // A: fp32, two [128x32] sub-tiles, 128B rows, SW128 (granule g of row r
    //    lands at g ^ (r&7)). Natural k-order fragments via ld.shared.v2.f32:
    //    a0 = k(2c,2c+1) at bytes grp*64+8c; a2 = +32; a1/a3 = row+8 (+1024B).
    // B: f16, one [64 rows x 64 k] tile, 128B rows, SW128. b0 = k(2c,2c+1) at
    //    bytes kq*32+4c (one LDS.32, already f16x2!); b1 = +16 bytes.
    const int mh   = wid & 3;         // 0..3: 32-row band
    const int kq   = wid >> 2;        // 0..3: k16 slice
    const int ksub = kq >> 1;         // which 32-k A sub-tile
    const int grp  = kq & 1;          // which k16 group within the A sub-tile
    const int c    = lid & 3;
    const uint32_t sw   = (uint32_t)(lid >> 2) << 4;    // swizzle XOR (row&7)*16
    const uint32_t aRow = (uint32_t)(mh * 32 + (lid >> 2));
    const uint32_t bRow = (uint32_t)(lid >> 2);

    // Constant per-warp byte offsets (within a 128B row, pre-XORed with sw).
    // No low-bit carries interact with the XORs (verified: 8c<=24, 4c<=12).
    const uint32_t aOff0 = ((uint32_t)(grp * 64 + 8 * c)) ^ sw;   // a0: k 2c,2c+1
    const uint32_t aOff2 = aOff0 ^ 32u;                            // a2: k +8
    const uint32_t bOff0 = ((uint32_t)(kq * 32 + 4 * c)) ^ sw;    // b0: k 2c,2c+1
    const uint32_t bOff1 = bOff0 ^ 16u;                            // b1: k +8

    float acc[2][8][4];   // [mt 16-row tiles][nt 8-col tiles][frag] = 64 regs
    #pragma unroll
    for (int mt = 0; mt < 2; mt++)
        #pragma unroll
        for (int nt = 0; nt < 8; nt++)
            #pragma unroll
            for (int i = 0; i < 4; i++) acc[mt][nt][i] = 0.0f;

    int st = 0, ph = 0;
    for (int it = 0; it < NITER; it++) {
        MBARRIER_WAIT_PARITY(sb + OFF_FULL + st * 8, ph);
        const char* base  = smem + OFF_DATA + st * STAGE_BYTES;
        const char* aBase = base + ksub * A_SUB;
        const char* bBase = base + A_BYTES;

        // B fragments: 8 n-tiles x 2 LDS.32, raw f16x2, no conversion.
        uint32_t bf[8][2];
        #pragma unroll
        for (int nt = 0; nt < 8; nt++) {
            const char* rp = bBase + (bRow + nt * 8) * 128;
            bf[nt][0] = *reinterpret_cast<const uint32_t*>(rp + bOff0);
            bf[nt][1] = *reinterpret_cast<const uint32_t*>(rp + bOff1);
        }

        #pragma unroll
        for (int mt = 0; mt < 2; mt++) {
            const char* ap = aBase + (aRow + mt * 16) * 128;
            const float2 f0 = *reinterpret_cast<const float2*>(ap + aOff0);
            const float2 f1 = *reinterpret_cast<const float2*>(ap + 1024 + aOff0);
            const float2 f2 = *reinterpret_cast<const float2*>(ap + aOff2);
            const float2 f3 = *reinterpret_cast<const float2*>(ap + 1024 + aOff2);
            uint32_t af[4];
            CVT_F16X2(af[0], f0.x, f0.y);
            CVT_F16X2(af[1], f1.x, f1.y);
            CVT_F16X2(af[2], f2.x, f2.y);
            CVT_F16X2(af[3], f3.x, f3.y);
            #pragma unroll
            for (int nt = 0; nt < 8; nt++)
                MMA_F16(acc[mt][nt], af, bf[nt]);
        }

        // HMMA issue implies all this stage's LDS completed -> safe to recycle.
        __syncwarp();
        if (lid == 0) MBARRIER_ARRIVE(sb + OFF_EMPTY + st * 8);
        if (++st == NSTAGE) { st = 0; ph ^= 1; }
    }

    // ---------------- 4-way cross-k reduction + epilogue ----------------
    // The 4 warps sharing mh reduce. kq=1..3 dump acc to SMEM ([j][lane],
    // conflict-free); after bar.sync, kq=0 sums 3 buffers + own acc, writes
    // GMEM. Stage data area is dead by now (12 x 8KB = 96KB < 200KB).
    {
        asm volatile("bar.sync 1, 512;" ::: "memory");   // all loop reads done
        float* redBase = reinterpret_cast<float*>(smem + OFF_DATA);
        if (kq != 0) {
            float* myBuf = redBase + (mh * 3 + (kq - 1)) * 2048;
            #pragma unroll
            for (int mt = 0; mt < 2; mt++)
                #pragma unroll
                for (int nt = 0; nt < 8; nt++)
                    #pragma unroll
                    for (int i = 0; i < 4; i++)
                        myBuf[((mt * 8 + nt) * 4 + i) * 32 + lid] = acc[mt][nt][i];
        }
        asm volatile("bar.sync 1, 512;" ::: "memory");
        if (kq == 0) {
            const float* r0 = redBase + (mh * 3 + 0) * 2048;
            const float* r1 = redBase + (mh * 3 + 1) * 2048;
            const float* r2 = redBase + (mh * 3 + 2) * 2048;
            #pragma unroll
            for (int mt = 0; mt < 2; mt++)
                #pragma unroll
                for (int nt = 0; nt < 8; nt++)
                    #pragma unroll
                    for (int i = 0; i < 4; i++) {
                        const int j = ((mt * 8 + nt) * 4 + i) * 32 + lid;
                        acc[mt][nt][i] += r0[j] + r1[j] + r2[j];
                    }

            // c0,c1 -> (row = lane/4, cols 2*(lane%4)+{0,1}); c2,c3 -> row+8.
            const size_t rowBase = (size_t)b * kS + (size_t)tile * TILE_M
                                 + (size_t)(mh * 32) + (size_t)(lid >> 2);
            const int colBase = (lid & 3) * 2;
            #pragma unroll
            for (int mt = 0; mt < 2; mt++) {
                #pragma unroll
                for (int nt = 0; nt < 8; nt++) {
                    const size_t r0w = rowBase + mt * 16;
                    float* p0 = out + r0w * kOUT + nt * 8 + colBase;
                    float* p1 = out + (r0w + 8) * kOUT + nt * 8 + colBase;
                    *reinterpret_cast<float2*>(p0) =
                        make_float2(acc[mt][nt][0], acc[mt][nt][1]);
                    *reinterpret_cast<float2*>(p1) =
                        make_float2(acc[mt][nt][2], acc[mt][nt][3]);
                }
            }
        }
    }
}

}  // namespace mlora

// ============================================================================
// Host side
// ============================================================================

typedef CUresult (*PFN_encodeTiled)(
    CUtensorMap*, CUtensorMapDataType, cuuint32_t, void*,
    const cuuint64_t*, const cuuint64_t*, const cuuint32_t*, const cuuint32_t*,
    CUtensorMapInterleave, CUtensorMapSwizzle, CUtensorMapL2promotion,
    CUtensorMapFloatOOBfill);

extern "C" void kernel_launch(void* const* d_in, const int* in_sizes, int n_in,
                              void* d_out, int out_size) {
    (void)in_sizes; (void)n_in; (void)out_size;
    const float* x   = (const float*)d_in[0];
    const int*   ids = (const int*)  d_in[1];
    const float* w   = (const float*)d_in[2];
    float*       out = (float*)d_out;

    PFN_encodeTiled enc = nullptr;
    {
        void* p = nullptr;
        cudaDriverEntryPointQueryResult qr;
#if CUDART_VERSION >= 12050
        cudaGetDriverEntryPointByVersion("cuTensorMapEncodeTiled", &p, 12000,
                                         cudaEnableDefault, &qr);
#else
        cudaGetDriverEntryPoint("cuTensorMapEncodeTiled", &p, cudaEnableDefault, &qr);
#endif
        enc = (PFN_encodeTiled)p;
    }

    void* wf16 = nullptr;
    cudaGetSymbolAddress(&wf16, g_wf16);

    CUtensorMap mapX, mapW;
    {
        // x: [B, S, IN] fp32 contiguous; dim0 = IN. Box = 32 x 128 (128B rows, SW128).
        cuuint64_t dims[3]    = {(cuuint64_t)mlora::kIN, (cuuint64_t)mlora::kS,
                                 (cuuint64_t)mlora::kB};
        cuuint64_t strides[2] = {(cuuint64_t)mlora::kIN * 4,
                                 (cuuint64_t)mlora::kS * mlora::kIN * 4};
        cuuint32_t box[3]     = {32, (cuuint32_t)mlora::TILE_M, 1};
        cuuint32_t es[3]      = {1, 1, 1};
        enc(&mapX, CU_TENSOR_MAP_DATA_TYPE_FLOAT32, 3, (void*)x,
            dims, strides, box, es,
            CU_TENSOR_MAP_INTERLEAVE_NONE, CU_TENSOR_MAP_SWIZZLE_128B,
            CU_TENSOR_MAP_L2_PROMOTION_L2_128B, CU_TENSOR_MAP_FLOAT_OOB_FILL_NONE);
    }
    {
        // wf16: [L, OUT, IN] f16 contiguous; dim0 = IN. Box = 64 x 64 (128B rows, SW128).
        cuuint64_t dims[3]    = {(cuuint64_t)mlora::kIN, (cuuint64_t)mlora::kOUT,
                                 (cuuint64_t)mlora::kL};
        cuuint64_t strides[2] = {(cuuint64_t)mlora::kIN * 2,
                                 (cuuint64_t)mlora::kOUT * mlora::kIN * 2};
        cuuint32_t box[3]     = {(cuuint32_t)mlora::TILE_K, (cuuint32_t)mlora::kOUT, 1};
        cuuint32_t es[3]      = {1, 1, 1};
        enc(&mapW, CU_TENSOR_MAP_DATA_TYPE_FLOAT16, 3, wf16,
            dims, strides, box, es,
            CU_TENSOR_MAP_INTERLEAVE_NONE, CU_TENSOR_MAP_SWIZZLE_128B,
            CU_TENSOR_MAP_L2_PROMOTION_L2_128B, CU_TENSOR_MAP_FLOAT_OOB_FILL_NONE);
    }

    // Prologue: convert referenced adapters' W fp32 -> f16 (deduped).
    mlora::convert_w_kernel<<<128, 256>>>((const float4*)w, (uint2*)wf16, ids);

    cudaFuncSetAttribute(mlora::mlora_kernel,
                         cudaFuncAttributeMaxDynamicSharedMemorySize,
                         mlora::SMEM_TOTAL);

    const int grid = mlora::kB * (mlora::kS / mlora::TILE_M);  // 128
    mlora::mlora_kernel<<<grid, mlora::NTHREADS, mlora::SMEM_TOTAL>>>(
        mapX, mapW, ids, out);
}

// round 15
// speedup vs baseline: 1.0393x; 1.0075x over previous
#include <cuda_runtime.h>
#include <cuda.h>
#include <cstdint>

// ============================================================================
// MultiLoraLinear on GB300 (ptxas target = plain sm_103, so NO tcgen05).
// Prologue kernel converts ONLY the referenced adapters' W fp32 -> f16
// scratch (deduped, 512 blocks, MLP-4 per thread, ~1.4us).
// Main: TMA + mbarrier pipeline -> SMEM -> mma.sync m16n8k16 f16.
//   out[b, s, o] = sum_i x[b, s, i] * weight[adapter_ids[b], o, i]
// B=8, S=2048, IN=4096, OUT=64, L=16, fp32 in/out.
//
// R15 vs R14 (bench 55.8 = main 48.3 + ~7.5 overhead; prologue was
// latency-bound: 128 blocks x 16 serial float4 round-trips):
//   Main kernel unchanged. Prologue re-shaped for MLP: 512 blocks
//   (8 b x 64 slices) x 256 thr, 4 independent float4 loads per thread,
//   fully unrolled -> ~1.2-1.5us at chip bandwidth.
// ============================================================================

#define DEVINL __device__ __forceinline__

namespace mlora {

constexpr int kB = 8, kS = 2048, kIN = 4096, kOUT = 64, kL = 16;
constexpr int TILE_M = 128;           // x rows per CTA
constexpr int TILE_K = 64;            // K elems per pipeline stage
constexpr int NITER  = kIN / TILE_K;  // 64
constexpr int NSTAGE = 5;

// Each stage: A = [128 rows x 64 k] fp32 as two [128 x 32] sub-tiles
// (128B rows, TMA SW128); B(W) = [64 rows x 64 k] f16, ONE tile, 128B rows.
constexpr int A_SUB   = TILE_M * 32 * 4;        // 16384
constexpr int A_BYTES = 2 * A_SUB;              // 32768
constexpr int B_BYTES = kOUT * TILE_K * 2;      //  8192 (f16)
constexpr int STAGE_BYTES = A_BYTES + B_BYTES;  // 40960

constexpr int OFF_FULL  = 0;
constexpr int OFF_EMPTY = OFF_FULL + NSTAGE * 8;
constexpr int OFF_DATA  = 1024;                              // SW128 alignment
constexpr int SMEM_TOTAL = OFF_DATA + NSTAGE * STAGE_BYTES;  // 205824

constexpr int NTHREADS = 544;          // 16 compute warps + 1 TMA warp
constexpr int W_ELEMS  = kL * kOUT * kIN;   // 4,194,304
constexpr int W_PER_AD = kOUT * kIN;        // 262,144 floats per adapter

}  // namespace mlora

// 8MB f16 scratch for converted weights ([L][OUT][IN], IN contiguous).
// Stored as raw 16-bit payloads; no fp16 header types needed.
__device__ __align__(16) uint16_t g_wf16[mlora::W_ELEMS];

namespace mlora {

DEVINL uint32_t smem_u32(const void* p) {
    uint32_t a;
    asm("{ .reg .u64 t; cvta.to.shared.u64 t, %1; cvt.u32.u64 %0, t; }"
        : "=r"(a) : "l"(p));
    return a;
}

DEVINL uint32_t elect_one() {
    uint32_t pred;
    asm volatile(
        "{\n\t.reg .pred p;\n\telect.sync _|p, 0xFFFFFFFF;\n\t"
        "selp.b32 %0, 1, 0, p;\n\t}"
        : "=r"(pred));
    return pred;
}

#define MBARRIER_INIT(mbar, count) \
    asm volatile("mbarrier.init.shared.b64 [%0], %1;" \
        :: "r"((uint32_t)(mbar)), "r"((uint32_t)(count)) : "memory")

#define MBARRIER_ARRIVE(mbar) \
    asm volatile("mbarrier.arrive.shared.b64 _, [%0];" \
        :: "r"((uint32_t)(mbar)) : "memory")

#define MBARRIER_EXPECT_TX(mbar, bytes) \
    asm volatile("mbarrier.arrive.expect_tx.shared.b64 _, [%0], %1;" \
        :: "r"((uint32_t)(mbar)), "r"((uint32_t)(bytes)) : "memory")

#define MBARRIER_WAIT_PARITY(mbar, parity) do {                                   \
    uint32_t _m = (uint32_t)(mbar);                                               \
    uint32_t _p = (uint32_t)(parity);                                             \
    uint32_t _done;                                                               \
    asm volatile(                                                                 \
        "{\n\t.reg .pred p;\n\t"                                                  \
        "mbarrier.try_wait.parity.acquire.cta.shared::cta.b64 p, [%1], %2;\n\t"   \
        "selp.b32 %0, 1, 0, p;\n\t}"                                              \
        : "=r"(_done) : "r"(_m), "r"(_p) : "memory");                             \
    if (!_done) {                                                                 \
        asm volatile(                                                             \
            "{\n\t.reg .pred P1;\n\t"                                             \
            "WAIT_LOOP_%=:\n\t"                                                   \
            "mbarrier.try_wait.parity.acquire.cta.shared::cta.b64 P1, [%0], %1, 0x989680;\n\t" \
            "@P1 bra.uni WAIT_DONE_%=;\n\t"                                       \
            "bra.uni WAIT_LOOP_%=;\n\t"                                           \
            "WAIT_DONE_%=:\n\t}"                                                  \
            :: "r"(_m), "r"(_p) : "memory");                                      \
    }                                                                             \
} while (0)

// Producer-side wait: post-wait SMEM writes are async-proxy (TMA) only.
#define MBARRIER_WAIT_PARITY_RELAXED(mbar, parity) do {                           \
    uint32_t _m = (uint32_t)(mbar);                                               \
    uint32_t _p = (uint32_t)(parity);                                             \
    uint32_t _done;                                                               \
    asm volatile(                                                                 \
        "{\n\t.reg .pred p;\n\t"                                                  \
        "mbarrier.try_wait.parity.relaxed.cta.shared::cta.b64 p, [%1], %2, 0x989680;\n\t" \
        "selp.b32 %0, 1, 0, p;\n\t}"                                              \
        : "=r"(_done) : "r"(_m), "r"(_p) : "memory");                             \
    if (!_done) {                                                                 \
        asm volatile(                                                             \
            "{\n\t.reg .pred P1;\n\t"                                             \
            "WAIT_LOOP_%=:\n\t"                                                   \
            "mbarrier.try_wait.parity.relaxed.cta.shared::cta.b64 P1, [%0], %1, 0x989680;\n\t" \
            "@P1 bra.uni WAIT_DONE_%=;\n\t"                                       \
            "bra.uni WAIT_LOOP_%=;\n\t"                                           \
            "WAIT_DONE_%=:\n\t}"                                                  \
            :: "r"(_m), "r"(_p) : "memory");                                      \
    }                                                                             \
} while (0)

#define TMA_LOAD_3D(smem_addr, tensor_map, cx, cy, cz, mbar) \
    asm volatile( \
        "cp.async.bulk.tensor.3d.shared::cta.global.tile.mbarrier::complete_tx::bytes " \
        "[%0], [%1, {%2, %3, %4}], [%5];" \
        :: "r"((uint32_t)(smem_addr)), "l"(tensor_map), \
           "r"((int32_t)(cx)), "r"((int32_t)(cy)), "r"((int32_t)(cz)), \
           "r"((uint32_t)(mbar)) \
        : "memory")

// Pack two f32 into one f16x2 register (rne): low half = vlo, high = vhi.
#define CVT_F16X2(dst, vlo, vhi) \
    asm("cvt.rn.f16x2.f32 %0, %1, %2;" : "=r"(dst) : "f"(vhi), "f"(vlo))

// m16n8k16 f16 MMA, fp32 accumulate (baseline PTX; fallback HMMA on sm_103).
#define MMA_F16(d, a, b) \
    asm volatile( \
        "mma.sync.aligned.m16n8k16.row.col.f32.f16.f16.f32 " \
        "{%0,%1,%2,%3}, {%4,%5,%6,%7}, {%8,%9}, {%0,%1,%2,%3};" \
        : "+f"((d)[0]), "+f"((d)[1]), "+f"((d)[2]), "+f"((d)[3]) \
        : "r"((a)[0]), "r"((a)[1]), "r"((a)[2]), "r"((a)[3]), \
          "r"((b)[0]), "r"((b)[1]))

// ============================================================================
// Prologue: convert ONLY referenced adapters' W fp32 -> f16 (rne; numerics
// identical to converting at use). Grid = 8 batches x 64 slices = 512 blocks,
// 256 threads, 4 independent float4 loads per thread (MLP-4, unrolled).
// Dedupe: the lowest batch index holding an adapter converts it.
// ============================================================================
__global__ void convert_w_kernel(const float4* __restrict__ w,
                                 uint2* __restrict__ dst,
                                 const int* __restrict__ ids) {
    const int b     = blockIdx.x >> 6;    // 0..7
    const int slice = blockIdx.x & 63;    // 0..63
    const int aid   = ids[b];
    for (int bb = 0; bb < b; bb++)
        if (ids[bb] == aid) return;        // another batch owns this adapter

    constexpr int PER = (W_PER_AD / 4) / 64;     // 1024 float4 per slice
    const float4* src = w   + (size_t)aid * (W_PER_AD / 4) + (size_t)slice * PER
                      + threadIdx.x;
    uint2*        d   = dst + (size_t)aid * (W_PER_AD / 4) + (size_t)slice * PER
                      + threadIdx.x;

    // 4 fully independent load/convert/store lanes (PER/256 = 4).
    float4 v0 = src[0];
    float4 v1 = src[256];
    float4 v2 = src[512];
    float4 v3 = src[768];
    uint2 o0, o1, o2, o3;
    CVT_F16X2(o0.x, v0.x, v0.y); CVT_F16X2(o0.y, v0.z, v0.w);
    CVT_F16X2(o1.x, v1.x, v1.y); CVT_F16X2(o1.y, v1.z, v1.w);
    CVT_F16X2(o2.x, v2.x, v2.y); CVT_F16X2(o2.y, v2.z, v2.w);
    CVT_F16X2(o3.x, v3.x, v3.y); CVT_F16X2(o3.y, v3.z, v3.w);
    d[0]   = o0;
    d[256] = o1;
    d[512] = o2;
    d[768] = o3;
}

// ============================================================================
// Main kernel: 544 threads. Warps 0-15 compute: warp w = (mh=w&3, kq=w>>2)
// owns rows [mh*32,+32) x all 64 cols over k16 slice kq of each stage.
// Natural k-order in both fragments (B is raw f16). Warp 16 = TMA producer.
// grid = B * (S/128) = 128. blockIdx.x = b*16 + tile. 1 CTA per SM.
// ============================================================================
__global__ void __launch_bounds__(NTHREADS, 1) mlora_kernel(
    const __grid_constant__ CUtensorMap mapX,
    const __grid_constant__ CUtensorMap mapW,
    const int* __restrict__ adapter_ids,
    float* __restrict__ out)
{
    extern __shared__ char smem[];
    const uint32_t sb = smem_u32(smem);
    const int tid  = threadIdx.x;
    const int wid  = tid >> 5;
    const int lid  = tid & 31;
    const int b    = blockIdx.x >> 4;
    const int tile = blockIdx.x & 15;

    if (tid == 0) {
        #pragma unroll
        for (int s = 0; s < NSTAGE; s++) {
            MBARRIER_INIT(sb + OFF_FULL  + s * 8, 1);   // completed by TMA tx bytes
            MBARRIER_INIT(sb + OFF_EMPTY + s * 8, 16);  // 16 consumer warps arrive
        }
    }
    __syncthreads();

    if (wid == 16) {
        // ---------------- TMA producer ----------------
        if (elect_one()) {
            const int aid = adapter_ids[b];
            int st = 0, ph = 1;  // parity 1: fresh empty barriers pass immediately
            for (int it = 0; it < NITER; it++) {
                MBARRIER_WAIT_PARITY_RELAXED(sb + OFF_EMPTY + st * 8, ph);
                const uint32_t full = sb + OFF_FULL + st * 8;
                MBARRIER_EXPECT_TX(full, STAGE_BYTES);
                const uint32_t base = sb + OFF_DATA + st * STAGE_BYTES;
                #pragma unroll
                for (int t = 0; t < 2; t++) {
                    TMA_LOAD_3D(base + t * A_SUB, &mapX,
                                it * TILE_K + t * 32, tile * TILE_M, b, full);
                }
                TMA_LOAD_3D(base + A_BYTES, &mapW, it * TILE_K, 0, aid, full);
                if (++st == NSTAGE) { st = 0; ph ^= 1; }
            }
        }
        return;
    }

    // ---------------- compute warps (wid 0..15) ----------------
    // Warp (mh, kq): rows [mh*32,+32) x cols [0,64), k16 slice kq.
    // A: fp32, two [128x32] sub-tiles, 128B rows, SW128 (granule g of row r
    //    lands at g ^ (r&7)). Natural k-order fragments via ld.shared.v2.f32:
    //    a0 = k(2c,2c+1) at bytes grp*64+8c; a2 = +32; a1/a3 = row+8 (+1024B).
    // B: f16, one [64 rows x 64 k] tile, 128B rows, SW128. b0 = k(2c,2c+1) at
    //    bytes kq*32+4c (one LDS.32, already f16x2!); b1 = +16 bytes.
    const int mh   = wid & 3;         // 0..3: 32-row band
    const int kq   = wid >> 2;        // 0..3: k16 slice
    const int ksub = kq >> 1;         // which 32-k A sub-tile
    const int grp  = kq & 1;          // which k16 group within the A sub-tile
    const int c    = lid & 3;
    const uint32_t sw   = (uint32_t)(lid >> 2) << 4;    // swizzle XOR (row&7)*16
    const uint32_t aRow = (uint32_t)(mh * 32 + (lid >> 2));
    const uint32_t bRow = (uint32_t)(lid >> 2);

    // Constant per-warp byte offsets (within a 128B row, pre-XORed with sw).
    // No low-bit carries interact with the XORs (verified: 8c<=24, 4c<=12).
    const uint32_t aOff0 = ((uint32_t)(grp * 64 + 8 * c)) ^ sw;   // a0: k 2c,2c+1
    const uint32_t aOff2 = aOff0 ^ 32u;                            // a2: k +8
    const uint32_t bOff0 = ((uint32_t)(kq * 32 + 4 * c)) ^ sw;    // b0: k 2c,2c+1
    const uint32_t bOff1 = bOff0 ^ 16u;                            // b1: k +8

    float acc[2][8][4];   // [mt 16-row tiles][nt 8-col tiles][frag] = 64 regs
    #pragma unroll
    for (int mt = 0; mt < 2; mt++)
        #pragma unroll
        for (int nt = 0; nt < 8; nt++)
            #pragma unroll
            for (int i = 0; i < 4; i++) acc[mt][nt][i] = 0.0f;

    int st = 0, ph = 0;
    for (int it = 0; it < NITER; it++) {
        MBARRIER_WAIT_PARITY(sb + OFF_FULL + st * 8, ph);
        const char* base  = smem + OFF_DATA + st * STAGE_BYTES;
        const char* aBase = base + ksub * A_SUB;
        const char* bBase = base + A_BYTES;

        // B fragments: 8 n-tiles x 2 LDS.32, raw f16x2, no conversion.
        uint32_t bf[8][2];
        #pragma unroll
        for (int nt = 0; nt < 8; nt++) {
            const char* rp = bBase + (bRow + nt * 8) * 128;
            bf[nt][0] = *reinterpret_cast<const uint32_t*>(rp + bOff0);
            bf[nt][1] = *reinterpret_cast<const uint32_t*>(rp + bOff1);
        }

        #pragma unroll
        for (int mt = 0; mt < 2; mt++) {
            const char* ap = aBase + (aRow + mt * 16) * 128;
            const float2 f0 = *reinterpret_cast<const float2*>(ap + aOff0);
            const float2 f1 = *reinterpret_cast<const float2*>(ap + 1024 + aOff0);
            const float2 f2 = *reinterpret_cast<const float2*>(ap + aOff2);
            const float2 f3 = *reinterpret_cast<const float2*>(ap + 1024 + aOff2);
            uint32_t af[4];
            CVT_F16X2(af[0], f0.x, f0.y);
            CVT_F16X2(af[1], f1.x, f1.y);
            CVT_F16X2(af[2], f2.x, f2.y);
            CVT_F16X2(af[3], f3.x, f3.y);
            #pragma unroll
            for (int nt = 0; nt < 8; nt++)
                MMA_F16(acc[mt][nt], af, bf[nt]);
        }

        // HMMA issue implies all this stage's LDS completed -> safe to recycle.
        __syncwarp();
        if (lid == 0) MBARRIER_ARRIVE(sb + OFF_EMPTY + st * 8);
        if (++st == NSTAGE) { st = 0; ph ^= 1; }
    }

    // ---------------- 4-way cross-k reduction + epilogue ----------------
    // The 4 warps sharing mh reduce. kq=1..3 dump acc to SMEM ([j][lane],
    // conflict-free); after bar.sync, kq=0 sums 3 buffers + own acc, writes
    // GMEM. Stage data area is dead by now (12 x 8KB = 96KB < 200KB).
    {
        asm volatile("bar.sync 1, 512;" ::: "memory");   // all loop reads done
        float* redBase = reinterpret_cast<float*>(smem + OFF_DATA);
        if (kq != 0) {
            float* myBuf = redBase + (mh * 3 + (kq - 1)) * 2048;
            #pragma unroll
            for (int mt = 0; mt < 2; mt++)
                #pragma unroll
                for (int nt = 0; nt < 8; nt++)
                    #pragma unroll
                    for (int i = 0; i < 4; i++)
                        myBuf[((mt * 8 + nt) * 4 + i) * 32 + lid] = acc[mt][nt][i];
        }
        asm volatile("bar.sync 1, 512;" ::: "memory");
        if (kq == 0) {
            const float* r0 = redBase + (mh * 3 + 0) * 2048;
            const float* r1 = redBase + (mh * 3 + 1) * 2048;
            const float* r2 = redBase + (mh * 3 + 2) * 2048;
            #pragma unroll
            for (int mt = 0; mt < 2; mt++)
                #pragma unroll
                for (int nt = 0; nt < 8; nt++)
                    #pragma unroll
                    for (int i = 0; i < 4; i++) {
                        const int j = ((mt * 8 + nt) * 4 + i) * 32 + lid;
                        acc[mt][nt][i] += r0[j] + r1[j] + r2[j];
                    }

            // c0,c1 -> (row = lane/4, cols 2*(lane%4)+{0,1}); c2,c3 -> row+8.
            const size_t rowBase = (size_t)b * kS + (size_t)tile * TILE_M
                                 + (size_t)(mh * 32) + (size_t)(lid >> 2);
            const int colBase = (lid & 3) * 2;
            #pragma unroll
            for (int mt = 0; mt < 2; mt++) {
                #pragma unroll
                for (int nt = 0; nt < 8; nt++) {
                    const size_t r0w = rowBase + mt * 16;
                    float* p0 = out + r0w * kOUT + nt * 8 + colBase;
                    float* p1 = out + (r0w + 8) * kOUT + nt * 8 + colBase;
                    *reinterpret_cast<float2*>(p0) =
                        make_float2(acc[mt][nt][0], acc[mt][nt][1]);
                    *reinterpret_cast<float2*>(p1) =
                        make_float2(acc[mt][nt][2], acc[mt][nt][3]);
                }
            }
        }
    }
}

}  // namespace mlora

// ============================================================================
// Host side
// ============================================================================

typedef CUresult (*PFN_encodeTiled)(
    CUtensorMap*, CUtensorMapDataType, cuuint32_t, void*,
    const cuuint64_t*, const cuuint64_t*, const cuuint32_t*, const cuuint32_t*,
    CUtensorMapInterleave, CUtensorMapSwizzle, CUtensorMapL2promotion,
    CUtensorMapFloatOOBfill);

extern "C" void kernel_launch(void* const* d_in, const int* in_sizes, int n_in,
                              void* d_out, int out_size) {
    (void)in_sizes; (void)n_in; (void)out_size;
    const float* x   = (const float*)d_in[0];
    const int*   ids = (const int*)  d_in[1];
    const float* w   = (const float*)d_in[2];
    float*       out = (float*)d_out;

    PFN_encodeTiled enc = nullptr;
    {
        void* p = nullptr;
        cudaDriverEntryPointQueryResult qr;
#if CUDART_VERSION >= 12050
        cudaGetDriverEntryPointByVersion("cuTensorMapEncodeTiled", &p, 12000,
                                         cudaEnableDefault, &qr);
#else
        cudaGetDriverEntryPoint("cuTensorMapEncodeTiled", &p, cudaEnableDefault, &qr);
#endif
        enc = (PFN_encodeTiled)p;
    }

    void* wf16 = nullptr;
    cudaGetSymbolAddress(&wf16, g_wf16);

    CUtensorMap mapX, mapW;
    {
        // x: [B, S, IN] fp32 contiguous; dim0 = IN. Box = 32 x 128 (128B rows, SW128).
        cuuint64_t dims[3]    = {(cuuint64_t)mlora::kIN, (cuuint64_t)mlora::kS,
                                 (cuuint64_t)mlora::kB};
        cuuint64_t strides[2] = {(cuuint64_t)mlora::kIN * 4,
                                 (cuuint64_t)mlora::kS * mlora::kIN * 4};
        cuuint32_t box[3]     = {32, (cuuint32_t)mlora::TILE_M, 1};
        cuuint32_t es[3]      = {1, 1, 1};
        enc(&mapX, CU_TENSOR_MAP_DATA_TYPE_FLOAT32, 3, (void*)x,
            dims, strides, box, es,
            CU_TENSOR_MAP_INTERLEAVE_NONE, CU_TENSOR_MAP_SWIZZLE_128B,
            CU_TENSOR_MAP_L2_PROMOTION_L2_128B, CU_TENSOR_MAP_FLOAT_OOB_FILL_NONE);
    }
    {
        // wf16: [L, OUT, IN] f16 contiguous; dim0 = IN. Box = 64 x 64 (128B rows, SW128).
        cuuint64_t dims[3]    = {(cuuint64_t)mlora::kIN, (cuuint64_t)mlora::kOUT,
                                 (cuuint64_t)mlora::kL};
        cuuint64_t strides[2] = {(cuuint64_t)mlora::kIN * 2,
                                 (cuuint64_t)mlora::kOUT * mlora::kIN * 2};
        cuuint32_t box[3]     = {(cuuint32_t)mlora::TILE_K, (cuuint32_t)mlora::kOUT, 1};
        cuuint32_t es[3]      = {1, 1, 1};
        enc(&mapW, CU_TENSOR_MAP_DATA_TYPE_FLOAT16, 3, wf16,
            dims, strides, box, es,
            CU_TENSOR_MAP_INTERLEAVE_NONE, CU_TENSOR_MAP_SWIZZLE_128B,
            CU_TENSOR_MAP_L2_PROMOTION_L2_128B, CU_TENSOR_MAP_FLOAT_OOB_FILL_NONE);
    }

    // Prologue: convert referenced adapters' W fp32 -> f16 (deduped, MLP-4).
    mlora::convert_w_kernel<<<512, 256>>>((const float4*)w, (uint2*)wf16, ids);

    cudaFuncSetAttribute(mlora::mlora_kernel,
                         cudaFuncAttributeMaxDynamicSharedMemorySize,
                         mlora::SMEM_TOTAL);

    const int grid = mlora::kB * (mlora::kS / mlora::TILE_M);  // 128
    mlora::mlora_kernel<<<grid, mlora::NTHREADS, mlora::SMEM_TOTAL>>>(
        mapX, mapW, ids, out);
}